// round 12
// baseline (speedup 1.0000x reference)
#include <cuda_runtime.h>
#include <math.h>

#define N_NODES 100000
#define NE      1600000
#define H1H     8
#define C1C     16
#define D1      128
#define NC      40
#define NEG     0.2f

// Scratch lives in __device__ globals referenced ONLY inside device code.
// (Passing these symbols as kernel args from host passes the host shadow
// address; on GB300 ATS that silently reads/writes host memory.)
__device__ __align__(256) float g_h1[N_NODES * D1];
__device__ __align__(256) float g_hrelu[N_NODES * D1];
__device__ __align__(256) float g_h2[N_NODES * NC];
__device__ __align__(256) float g_ssrc1[N_NODES * H1H];
__device__ __align__(256) float g_sdst1[N_NODES * H1H];
__device__ __align__(256) float g_ssrc2[N_NODES];
__device__ __align__(256) float g_sdst2[N_NODES];
__device__ __align__(256) int   g_deg[N_NODES];
__device__ __align__(256) int   g_cur[N_NODES];
__device__ __align__(256) int   g_off[N_NODES + 1];
__device__ __align__(256) int   g_srt[NE];
__device__ __align__(256) int   g_src[NE];
__device__ __align__(256) int   g_dst[NE];

#define SCAN_B 1024
#define NSB ((N_NODES + SCAN_B - 1) / SCAN_B)
__device__ __align__(256) int g_part[NSB];

__device__ __forceinline__ float lrelu(float x) { return x > 0.f ? x : NEG * x; }

// ---- edge decode (int32 planar — proven by R10 recon) ----
__global__ void k_convert(const int* __restrict__ ei) {
    int e = blockIdx.x * blockDim.x + threadIdx.x;
    if (e < NE) { g_src[e] = ei[e]; g_dst[e] = ei[NE + e]; }
}

// ---- CSR build ----
__global__ void k_zero() {
    int i = blockIdx.x * blockDim.x + threadIdx.x;
    if (i < N_NODES) { g_deg[i] = 0; g_cur[i] = 0; }
}
__global__ void k_hist() {
    int e = blockIdx.x * blockDim.x + threadIdx.x;
    if (e < NE) atomicAdd(&g_deg[g_dst[e]], 1);
}
__global__ void k_scan1() {
    __shared__ int s[SCAN_B];
    int t = threadIdx.x, i = blockIdx.x * SCAN_B + t;
    int v = (i < N_NODES) ? g_deg[i] : 0;
    s[t] = v; __syncthreads();
    for (int d = 1; d < SCAN_B; d <<= 1) {
        int x = (t >= d) ? s[t - d] : 0; __syncthreads();
        s[t] += x; __syncthreads();
    }
    if (i < N_NODES) g_off[i] = s[t] - v;
    if (t == SCAN_B - 1) g_part[blockIdx.x] = s[t];
}
__global__ void k_scan2() {
    if (threadIdx.x == 0) {
        int acc = 0;
        for (int i = 0; i < NSB; i++) { int x = g_part[i]; g_part[i] = acc; acc += x; }
    }
}
__global__ void k_scan3() {
    int i = blockIdx.x * blockDim.x + threadIdx.x;
    if (i < N_NODES) g_off[i] += g_part[i >> 10];
    if (i == 0) g_off[N_NODES] = NE;
}
__global__ void k_scatter() {
    int e = blockIdx.x * blockDim.x + threadIdx.x;
    if (e < NE) {
        int d = g_dst[e];
        int pos = g_off[d] + atomicAdd(&g_cur[d], 1);
        g_srt[pos] = g_src[e];
    }
}

// ---- GEMM1: g_h1[M][128] = x[M][128] * W1[128][128] ----
__global__ void k_gemm1(const float* __restrict__ A, const float* __restrict__ B) {
    __shared__ float As[16][132];
    __shared__ float Bs[16][132];
    int tid = threadIdx.x, tx = tid & 15, ty = tid >> 4;
    int row0 = blockIdx.x * 128, r0 = ty * 8, c0 = tx * 8;
    float acc[8][8];
#pragma unroll
    for (int i = 0; i < 8; i++)
#pragma unroll
        for (int j = 0; j < 8; j++) acc[i][j] = 0.f;
    for (int kb = 0; kb < 128; kb += 16) {
        for (int l = tid; l < 2048; l += 256) {
            int r = l >> 4, kk = l & 15, row = row0 + r;
            As[kk][r] = (row < N_NODES) ? A[row * 128 + kb + kk] : 0.f;
        }
        for (int l = tid; l < 2048; l += 256) {
            int kk = l >> 7, col = l & 127;
            Bs[kk][col] = B[(kb + kk) * 128 + col];
        }
        __syncthreads();
#pragma unroll
        for (int kk = 0; kk < 16; kk++) {
            float a[8], b[8];
#pragma unroll
            for (int i = 0; i < 8; i++) a[i] = As[kk][r0 + i];
#pragma unroll
            for (int j = 0; j < 8; j++) b[j] = Bs[kk][c0 + j];
#pragma unroll
            for (int i = 0; i < 8; i++)
#pragma unroll
                for (int j = 0; j < 8; j++) acc[i][j] += a[i] * b[j];
        }
        __syncthreads();
    }
#pragma unroll
    for (int i = 0; i < 8; i++) {
        int row = row0 + r0 + i;
        if (row >= N_NODES) continue;
#pragma unroll
        for (int j = 0; j < 8; j++) g_h1[row * 128 + c0 + j] = acc[i][j];
    }
}

// ---- GEMM2: g_h2[M][40] = g_hrelu[M][128] * W2[128][40] ----
__global__ void k_gemm2(const float* __restrict__ B) {
    __shared__ float As[16][132];
    __shared__ float Bs[16][48];
    int tid = threadIdx.x, tx = tid & 15, ty = tid >> 4;
    int row0 = blockIdx.x * 128, r0 = ty * 8;
    float acc[8][3];
#pragma unroll
    for (int i = 0; i < 8; i++)
#pragma unroll
        for (int j = 0; j < 3; j++) acc[i][j] = 0.f;
    for (int kb = 0; kb < 128; kb += 16) {
        for (int l = tid; l < 2048; l += 256) {
            int r = l >> 4, kk = l & 15, row = row0 + r;
            As[kk][r] = (row < N_NODES) ? g_hrelu[row * 128 + kb + kk] : 0.f;
        }
        for (int l = tid; l < 640; l += 256) {
            int kk = l / 40, col = l % 40;
            Bs[kk][col] = B[(kb + kk) * 40 + col];
        }
        __syncthreads();
#pragma unroll
        for (int kk = 0; kk < 16; kk++) {
            float a[8];
#pragma unroll
            for (int i = 0; i < 8; i++) a[i] = As[kk][r0 + i];
            float b0 = Bs[kk][tx], b1 = Bs[kk][tx + 16], b2 = (tx < 8) ? Bs[kk][tx + 32] : 0.f;
#pragma unroll
            for (int i = 0; i < 8; i++) {
                acc[i][0] += a[i] * b0; acc[i][1] += a[i] * b1; acc[i][2] += a[i] * b2;
            }
        }
        __syncthreads();
    }
#pragma unroll
    for (int i = 0; i < 8; i++) {
        int row = row0 + r0 + i;
        if (row >= N_NODES) continue;
        g_h2[row * 40 + tx] = acc[i][0];
        g_h2[row * 40 + tx + 16] = acc[i][1];
        if (tx < 8) g_h2[row * 40 + tx + 32] = acc[i][2];
    }
}

// ---- per-node attention logits ----
__global__ void k_s1(const float* __restrict__ a_src, const float* __restrict__ a_dst) {
    int i = blockIdx.x * blockDim.x + threadIdx.x;
    if (i >= N_NODES * H1H) return;
    int n = i >> 3, h = i & 7;
    const float* hp = &g_h1[n * D1 + h * C1C];
    float ss = 0.f, sd = 0.f;
#pragma unroll
    for (int c = 0; c < C1C; c++) {
        float v = hp[c];
        ss += v * a_src[h * C1C + c];
        sd += v * a_dst[h * C1C + c];
    }
    g_ssrc1[i] = ss; g_sdst1[i] = sd;
}
__global__ void k_s2(const float* __restrict__ a_src, const float* __restrict__ a_dst) {
    int n = blockIdx.x * blockDim.x + threadIdx.x;
    if (n >= N_NODES) return;
    float ss = 0.f, sd = 0.f;
#pragma unroll
    for (int c = 0; c < NC; c++) {
        float v = g_h2[n * NC + c];
        ss += v * a_src[c];
        sd += v * a_dst[c];
    }
    g_ssrc2[n] = ss; g_sdst2[n] = sd;
}

// ---- layer1 aggregation: warp per dst node ----
__global__ void k_agg1(const float* __restrict__ b1) {
    int warp = (blockIdx.x * blockDim.x + threadIdx.x) >> 5;
    int lane = threadIdx.x & 31;
    if (warp >= N_NODES) return;
    int i = warp, h = lane >> 2;
    float sdst = g_sdst1[i * H1H + h];
    float eself = lrelu(g_ssrc1[i * H1H + h] + sdst);
    int beg = g_off[i], end = g_off[i + 1];
    float maxv = eself;
    for (int j = beg; j < end; j++)
        maxv = fmaxf(maxv, lrelu(g_ssrc1[g_srt[j] * H1H + h] + sdst));
    const float4* hp = (const float4*)g_h1;
    float denom = __expf(eself - maxv);
    float4 v = hp[i * 32 + lane];
    float4 acc = {denom * v.x, denom * v.y, denom * v.z, denom * v.w};
    for (int j = beg; j < end; j++) {
        int s = g_srt[j];
        float p = __expf(lrelu(g_ssrc1[s * H1H + h] + sdst) - maxv);
        denom += p;
        float4 w = hp[s * 32 + lane];
        acc.x += p * w.x; acc.y += p * w.y; acc.z += p * w.z; acc.w += p * w.w;
    }
    float inv = 1.f / denom;
    float4 o;
    o.x = fmaxf(acc.x * inv + b1[lane * 4 + 0], 0.f);
    o.y = fmaxf(acc.y * inv + b1[lane * 4 + 1], 0.f);
    o.z = fmaxf(acc.z * inv + b1[lane * 4 + 2], 0.f);
    o.w = fmaxf(acc.w * inv + b1[lane * 4 + 3], 0.f);
    ((float4*)g_hrelu)[i * 32 + lane] = o;
}

// ---- layer2 aggregation + log_softmax ----
__global__ void k_agg2(const float* __restrict__ b2, float* __restrict__ out) {
    int warp = (blockIdx.x * blockDim.x + threadIdx.x) >> 5;
    int lane = threadIdx.x & 31;
    if (warp >= N_NODES) return;
    int i = warp;
    float sdst = g_sdst2[i];
    float eself = lrelu(g_ssrc2[i] + sdst);
    int beg = g_off[i], end = g_off[i + 1];
    float maxv = eself;
    for (int j = beg; j < end; j++)
        maxv = fmaxf(maxv, lrelu(g_ssrc2[g_srt[j]] + sdst));
    float denom = __expf(eself - maxv);
    float a0 = denom * g_h2[i * NC + lane];
    float a1 = (lane < 8) ? denom * g_h2[i * NC + 32 + lane] : 0.f;
    for (int j = beg; j < end; j++) {
        int s = g_srt[j];
        float p = __expf(lrelu(g_ssrc2[s] + sdst) - maxv);
        denom += p;
        a0 += p * g_h2[s * NC + lane];
        if (lane < 8) a1 += p * g_h2[s * NC + 32 + lane];
    }
    float inv = 1.f / denom;
    float v0 = a0 * inv + b2[lane];
    float v1 = (lane < 8) ? (a1 * inv + b2[32 + lane]) : -INFINITY;
    float m = fmaxf(v0, v1);
#pragma unroll
    for (int d = 16; d; d >>= 1) m = fmaxf(m, __shfl_xor_sync(0xffffffffu, m, d));
    float se = __expf(v0 - m) + ((lane < 8) ? __expf(v1 - m) : 0.f);
#pragma unroll
    for (int d = 16; d; d >>= 1) se += __shfl_xor_sync(0xffffffffu, se, d);
    float ls = m + logf(se);
    out[i * NC + lane] = v0 - ls;
    if (lane < 8) out[i * NC + 32 + lane] = v1 - ls;
}

// ---- launch ----
extern "C" void kernel_launch(void* const* d_in, const int* in_sizes, int n_in,
                              void* d_out, int out_size) {
    const float* x   = (const float*)d_in[0];
    const int*   ei  = (const int*)d_in[1];
    const float* W1  = (const float*)d_in[2];
    const float* as1 = (const float*)d_in[3];
    const float* ad1 = (const float*)d_in[4];
    const float* b1  = (const float*)d_in[5];
    const float* W2  = (const float*)d_in[6];
    const float* as2 = (const float*)d_in[7];
    const float* ad2 = (const float*)d_in[8];
    const float* b2  = (const float*)d_in[9];
    float* out = (float*)d_out;

    k_convert<<<(NE + 255) / 256, 256>>>(ei);
    k_zero<<<(N_NODES + 255) / 256, 256>>>();
    k_hist<<<(NE + 255) / 256, 256>>>();
    k_scan1<<<NSB, SCAN_B>>>();
    k_scan2<<<1, 32>>>();
    k_scan3<<<(N_NODES + 1023) / 1024, 1024>>>();
    k_scatter<<<(NE + 255) / 256, 256>>>();

    k_gemm1<<<(N_NODES + 127) / 128, 256>>>(x, W1);
    k_s1<<<(N_NODES * H1H + 255) / 256, 256>>>(as1, ad1);
    k_agg1<<<(N_NODES * 32 + 255) / 256, 256>>>(b1);

    k_gemm2<<<(N_NODES + 127) / 128, 256>>>(W2);
    k_s2<<<(N_NODES + 255) / 256, 256>>>(as2, ad2);
    k_agg2<<<(N_NODES * 32 + 255) / 256, 256>>>(b2, out);
}

// round 13
// speedup vs baseline: 1.0850x; 1.0850x over previous
#include <cuda_runtime.h>
#include <math.h>

#define N_NODES 100000
#define NE      1600000
#define H1H     8
#define C1C     16
#define D1      128
#define NC      40
#define NEG     0.2f

// Scratch: __device__ globals referenced ONLY inside device code (GB300 ATS
// trap: passing the symbol as a kernel arg from host passes the host shadow).
__device__ __align__(256) float g_h1[N_NODES * D1];
__device__ __align__(256) float g_hrelu[N_NODES * D1];
__device__ __align__(256) float g_h2[N_NODES * NC];
__device__ __align__(256) float g_ssrc1[N_NODES * H1H];
__device__ __align__(256) float g_sdst1[N_NODES * H1H];
__device__ __align__(256) float g_ssrc2[N_NODES];
__device__ __align__(256) float g_sdst2[N_NODES];
__device__ __align__(256) int   g_deg[N_NODES];
__device__ __align__(256) int   g_cur[N_NODES];
__device__ __align__(256) int   g_off[N_NODES + 1];
__device__ __align__(256) int   g_srt[NE];

#define SCAN_B 1024
#define NSB ((N_NODES + SCAN_B - 1) / SCAN_B)   /* 98 */
__device__ __align__(256) int g_part[NSB];

__device__ __forceinline__ float lrelu(float x) { return x > 0.f ? x : NEG * x; }

// ---- CSR build (edge_index: int32 planar, proven by recon) ----
__global__ void k_zero() {
    int i = blockIdx.x * blockDim.x + threadIdx.x;
    if (i < N_NODES) { g_deg[i] = 0; g_cur[i] = 0; }
}
__global__ void k_hist(const int* __restrict__ ei) {
    int e = blockIdx.x * blockDim.x + threadIdx.x;
    if (e < NE) atomicAdd(&g_deg[ei[NE + e]], 1);
}
__global__ void k_scan1() {
    __shared__ int s[SCAN_B];
    int t = threadIdx.x, i = blockIdx.x * SCAN_B + t;
    int v = (i < N_NODES) ? g_deg[i] : 0;
    s[t] = v; __syncthreads();
    for (int d = 1; d < SCAN_B; d <<= 1) {
        int x = (t >= d) ? s[t - d] : 0; __syncthreads();
        s[t] += x; __syncthreads();
    }
    if (i < N_NODES) g_off[i] = s[t] - v;
    if (t == SCAN_B - 1) g_part[blockIdx.x] = s[t];
}
__global__ void k_scan2() {   // parallel block-scan over the 98 partials
    __shared__ int s[128];
    int t = threadIdx.x;
    int v = (t < NSB) ? g_part[t] : 0;
    s[t] = v; __syncthreads();
    for (int d = 1; d < 128; d <<= 1) {
        int x = (t >= d) ? s[t - d] : 0; __syncthreads();
        s[t] += x; __syncthreads();
    }
    if (t < NSB) g_part[t] = s[t] - v;   // exclusive
}
__global__ void k_scan3() {
    int i = blockIdx.x * blockDim.x + threadIdx.x;
    if (i < N_NODES) g_off[i] += g_part[i >> 10];
    if (i == 0) g_off[N_NODES] = NE;
}
__global__ void k_scatter(const int* __restrict__ ei) {
    int e = blockIdx.x * blockDim.x + threadIdx.x;
    if (e < NE) {
        int d = ei[NE + e];
        int pos = g_off[d] + atomicAdd(&g_cur[d], 1);
        g_srt[pos] = ei[e];
    }
}

// ---- GEMM1 (BK=32, float4 loads) + fused s1 logits ----
__global__ void k_gemm1s(const float* __restrict__ A, const float* __restrict__ B,
                         const float* __restrict__ as1, const float* __restrict__ ad1) {
    __shared__ float As[32][132];   // [kk][row]
    __shared__ float Bs[32][132];   // [kk][col]
    int tid = threadIdx.x, tx = tid & 15, ty = tid >> 4;
    int row0 = blockIdx.x * 128, r0 = ty * 8, c0 = tx * 8;
    float acc[8][8];
#pragma unroll
    for (int i = 0; i < 8; i++)
#pragma unroll
        for (int j = 0; j < 8; j++) acc[i][j] = 0.f;

    for (int kb = 0; kb < 128; kb += 32) {
        // A tile: 128 rows x 32 cols = 1024 float4; 4 per thread (transposed store)
#pragma unroll
        for (int q = 0; q < 4; q++) {
            int f = tid + 256 * q;
            int r = f >> 3, c4 = f & 7;
            int row = row0 + r;
            float4 v = (row < N_NODES)
                       ? *(const float4*)&A[row * 128 + kb + c4 * 4]
                       : make_float4(0.f, 0.f, 0.f, 0.f);
            As[c4 * 4 + 0][r] = v.x;
            As[c4 * 4 + 1][r] = v.y;
            As[c4 * 4 + 2][r] = v.z;
            As[c4 * 4 + 3][r] = v.w;
        }
        // B tile: 32 rows x 128 cols = 1024 float4; direct float4 store
#pragma unroll
        for (int q = 0; q < 4; q++) {
            int f = tid + 256 * q;
            int kk = f >> 5, c4 = f & 31;
            float4 v = *(const float4*)&B[(kb + kk) * 128 + c4 * 4];
            *(float4*)&Bs[kk][c4 * 4] = v;
        }
        __syncthreads();
#pragma unroll
        for (int kk = 0; kk < 32; kk++) {
            float a[8], b[8];
#pragma unroll
            for (int i = 0; i < 8; i++) a[i] = As[kk][r0 + i];
#pragma unroll
            for (int j = 0; j < 8; j++) b[j] = Bs[kk][c0 + j];
#pragma unroll
            for (int i = 0; i < 8; i++)
#pragma unroll
                for (int j = 0; j < 8; j++) acc[i][j] += a[i] * b[j];
        }
        __syncthreads();
    }

    // epilogue: write h1 + fused s1 partial dots
    int h = tx >> 1;                   // head of this thread's 8 columns
    int cb = h * C1C + (tx & 1) * 8;   // att-vector base for these columns
    float av[8], dv[8];
#pragma unroll
    for (int j = 0; j < 8; j++) { av[j] = as1[cb + j]; dv[j] = ad1[cb + j]; }

#pragma unroll
    for (int i = 0; i < 8; i++) {
        int row = row0 + r0 + i;
        if (row >= N_NODES) continue;
        float4 lo = make_float4(acc[i][0], acc[i][1], acc[i][2], acc[i][3]);
        float4 hi = make_float4(acc[i][4], acc[i][5], acc[i][6], acc[i][7]);
        *(float4*)&g_h1[row * 128 + c0] = lo;
        *(float4*)&g_h1[row * 128 + c0 + 4] = hi;
        float ps = 0.f, pd = 0.f;
#pragma unroll
        for (int j = 0; j < 8; j++) { ps += acc[i][j] * av[j]; pd += acc[i][j] * dv[j]; }
        ps += __shfl_xor_sync(0xffffffffu, ps, 1);
        pd += __shfl_xor_sync(0xffffffffu, pd, 1);
        if ((tx & 1) == 0) {
            g_ssrc1[row * H1H + h] = ps;
            g_sdst1[row * H1H + h] = pd;
        }
    }
}

// ---- GEMM2 + fused s2 logits ----
__global__ void k_gemm2s(const float* __restrict__ B,
                         const float* __restrict__ as2, const float* __restrict__ ad2) {
    __shared__ float As[16][132];
    __shared__ float Bs[16][48];
    int tid = threadIdx.x, tx = tid & 15, ty = tid >> 4;
    int row0 = blockIdx.x * 128, r0 = ty * 8;
    float acc[8][3];
#pragma unroll
    for (int i = 0; i < 8; i++)
#pragma unroll
        for (int j = 0; j < 3; j++) acc[i][j] = 0.f;
    for (int kb = 0; kb < 128; kb += 16) {
        for (int l = tid; l < 2048; l += 256) {
            int r = l >> 4, kk = l & 15, row = row0 + r;
            As[kk][r] = (row < N_NODES) ? g_hrelu[row * 128 + kb + kk] : 0.f;
        }
        for (int l = tid; l < 640; l += 256) {
            int kk = l / 40, col = l % 40;
            Bs[kk][col] = B[(kb + kk) * 40 + col];
        }
        __syncthreads();
#pragma unroll
        for (int kk = 0; kk < 16; kk++) {
            float a[8];
#pragma unroll
            for (int i = 0; i < 8; i++) a[i] = As[kk][r0 + i];
            float b0 = Bs[kk][tx], b1 = Bs[kk][tx + 16], b2 = (tx < 8) ? Bs[kk][tx + 32] : 0.f;
#pragma unroll
            for (int i = 0; i < 8; i++) {
                acc[i][0] += a[i] * b0; acc[i][1] += a[i] * b1; acc[i][2] += a[i] * b2;
            }
        }
        __syncthreads();
    }
    float a0 = as2[tx], a1 = as2[tx + 16], a2 = (tx < 8) ? as2[tx + 32] : 0.f;
    float d0 = ad2[tx], d1 = ad2[tx + 16], d2 = (tx < 8) ? ad2[tx + 32] : 0.f;
#pragma unroll
    for (int i = 0; i < 8; i++) {
        int row = row0 + r0 + i;
        if (row >= N_NODES) continue;
        g_h2[row * 40 + tx] = acc[i][0];
        g_h2[row * 40 + tx + 16] = acc[i][1];
        if (tx < 8) g_h2[row * 40 + tx + 32] = acc[i][2];
        float ps = acc[i][0] * a0 + acc[i][1] * a1 + acc[i][2] * a2;
        float pd = acc[i][0] * d0 + acc[i][1] * d1 + acc[i][2] * d2;
#pragma unroll
        for (int o = 8; o; o >>= 1) {   // reduce across the 16 tx lanes
            ps += __shfl_xor_sync(0xffffffffu, ps, o);
            pd += __shfl_xor_sync(0xffffffffu, pd, o);
        }
        if (tx == 0) { g_ssrc2[row] = ps; g_sdst2[row] = pd; }
    }
}

// ---- layer1 aggregation: warp/node, single-pass online softmax ----
__global__ void k_agg1(const float* __restrict__ b1) {
    int warp = (blockIdx.x * blockDim.x + threadIdx.x) >> 5;
    int lane = threadIdx.x & 31;
    if (warp >= N_NODES) return;
    int i = warp, h = lane >> 2;
    float sdst = g_sdst1[i * H1H + h];
    float m = lrelu(g_ssrc1[i * H1H + h] + sdst);   // self logit
    int beg = g_off[i], end = g_off[i + 1];
    const float4* hp = (const float4*)g_h1;
    float den = 1.f;                                 // exp(self - m) = 1
    float4 acc = hp[i * 32 + lane];
    int s = (beg < end) ? g_srt[beg] : 0;
    for (int j = beg; j < end; j++) {
        int snext = (j + 1 < end) ? g_srt[j + 1] : 0;
        float e = lrelu(g_ssrc1[s * H1H + h] + sdst);
        float p;
        if (e > m) {
            float sc = __expf(m - e);
            den *= sc;
            acc.x *= sc; acc.y *= sc; acc.z *= sc; acc.w *= sc;
            m = e; p = 1.f;
        } else {
            p = __expf(e - m);
        }
        float4 w = hp[s * 32 + lane];
        den += p;
        acc.x += p * w.x; acc.y += p * w.y; acc.z += p * w.z; acc.w += p * w.w;
        s = snext;
    }
    float inv = 1.f / den;
    float4 o;
    o.x = fmaxf(acc.x * inv + b1[lane * 4 + 0], 0.f);
    o.y = fmaxf(acc.y * inv + b1[lane * 4 + 1], 0.f);
    o.z = fmaxf(acc.z * inv + b1[lane * 4 + 2], 0.f);
    o.w = fmaxf(acc.w * inv + b1[lane * 4 + 3], 0.f);
    ((float4*)g_hrelu)[i * 32 + lane] = o;
}

// ---- layer2 aggregation (online softmax) + log_softmax ----
__global__ void k_agg2(const float* __restrict__ b2, float* __restrict__ out) {
    int warp = (blockIdx.x * blockDim.x + threadIdx.x) >> 5;
    int lane = threadIdx.x & 31;
    if (warp >= N_NODES) return;
    int i = warp;
    float sdst = g_sdst2[i];
    float m = lrelu(g_ssrc2[i] + sdst);
    int beg = g_off[i], end = g_off[i + 1];
    float den = 1.f;
    float a0 = g_h2[i * NC + lane];
    float a1 = (lane < 8) ? g_h2[i * NC + 32 + lane] : 0.f;
    int s = (beg < end) ? g_srt[beg] : 0;
    for (int j = beg; j < end; j++) {
        int snext = (j + 1 < end) ? g_srt[j + 1] : 0;
        float e = lrelu(g_ssrc2[s] + sdst);
        float p;
        if (e > m) {
            float sc = __expf(m - e);
            den *= sc; a0 *= sc; a1 *= sc;
            m = e; p = 1.f;
        } else {
            p = __expf(e - m);
        }
        den += p;
        a0 += p * g_h2[s * NC + lane];
        if (lane < 8) a1 += p * g_h2[s * NC + 32 + lane];
        s = snext;
    }
    float inv = 1.f / den;
    float v0 = a0 * inv + b2[lane];
    float v1 = (lane < 8) ? (a1 * inv + b2[32 + lane]) : -INFINITY;
    float mm = fmaxf(v0, v1);
#pragma unroll
    for (int d = 16; d; d >>= 1) mm = fmaxf(mm, __shfl_xor_sync(0xffffffffu, mm, d));
    float se = __expf(v0 - mm) + ((lane < 8) ? __expf(v1 - mm) : 0.f);
#pragma unroll
    for (int d = 16; d; d >>= 1) se += __shfl_xor_sync(0xffffffffu, se, d);
    float ls = mm + logf(se);
    out[i * NC + lane] = v0 - ls;
    if (lane < 8) out[i * NC + 32 + lane] = v1 - ls;
}

// ---- launch ----
extern "C" void kernel_launch(void* const* d_in, const int* in_sizes, int n_in,
                              void* d_out, int out_size) {
    const float* x   = (const float*)d_in[0];
    const int*   ei  = (const int*)d_in[1];
    const float* W1  = (const float*)d_in[2];
    const float* as1 = (const float*)d_in[3];
    const float* ad1 = (const float*)d_in[4];
    const float* b1  = (const float*)d_in[5];
    const float* W2  = (const float*)d_in[6];
    const float* as2 = (const float*)d_in[7];
    const float* ad2 = (const float*)d_in[8];
    const float* b2  = (const float*)d_in[9];
    float* out = (float*)d_out;

    k_zero<<<(N_NODES + 255) / 256, 256>>>();
    k_hist<<<(NE + 255) / 256, 256>>>(ei);
    k_scan1<<<NSB, SCAN_B>>>();
    k_scan2<<<1, 128>>>();
    k_scan3<<<(N_NODES + 1023) / 1024, 1024>>>();
    k_scatter<<<(NE + 255) / 256, 256>>>(ei);

    k_gemm1s<<<(N_NODES + 127) / 128, 256>>>(x, W1, as1, ad1);
    k_agg1<<<(N_NODES * 32 + 255) / 256, 256>>>(b1);

    k_gemm2s<<<(N_NODES + 127) / 128, 256>>>(W2, as2, ad2);
    k_agg2<<<(N_NODES * 32 + 255) / 256, 256>>>(b2, out);
}